// round 1
// baseline (speedup 1.0000x reference)
#include <cuda_runtime.h>
#include <cstdint>
#include <math_constants.h>

#define BM   64
#define BN   64
#define DK   64
#define SLEN 1024
#define QLEN 1024
#define NBH  32
#define PAD  68   // 32-bit-word stride for 64-wide smem tiles (conflict padding)

__device__ __forceinline__ uint32_t f2tf(float x) {
    uint32_t r; asm("cvt.rna.tf32.f32 %0, %1;" : "=r"(r) : "f"(x)); return r;
}

__device__ __forceinline__ void mma_tf32(float c[4],
    uint32_t a0, uint32_t a1, uint32_t a2, uint32_t a3,
    uint32_t b0, uint32_t b1)
{
    asm volatile(
        "mma.sync.aligned.m16n8k8.row.col.f32.tf32.tf32.f32 "
        "{%0,%1,%2,%3}, {%4,%5,%6,%7}, {%8,%9}, {%0,%1,%2,%3};"
        : "+f"(c[0]), "+f"(c[1]), "+f"(c[2]), "+f"(c[3])
        : "r"(a0), "r"(a1), "r"(a2), "r"(a3), "r"(b0), "r"(b1));
}

struct __align__(16) Smem {
    union {
        struct { uint32_t Qs[BM * PAD]; uint32_t Ks[DK * PAD]; } a;  // phase A
        struct { uint32_t Ps[BM * PAD]; uint32_t Vs[BN * PAD]; } b;  // phase B
    } u;
    float rowmax[BM];
    float rowinv[BM];
};

__global__ void __launch_bounds__(256)
attn_kernel(const float* __restrict__ q, const float* __restrict__ k,
            const float* __restrict__ v, const float* __restrict__ prev,
            const float* __restrict__ scale_p,
            float* __restrict__ outO, float* __restrict__ outW,
            float* __restrict__ outS)
{
    __shared__ Smem sm;
    const int tid  = threadIdx.x;
    const int bh   = blockIdx.y;
    const int m0   = blockIdx.x * BM;
    const int warp = tid >> 5, lane = tid & 31;
    const int g    = lane >> 2, t4 = lane & 3;    // groupID, threadID_in_group
    const int wm   = warp & 3;                    // 4 warp-tiles of 16 rows
    const int wn   = warp >> 2;                   // 2 warp-tiles of 32 cols
    const float scale = scale_p[0];

    const float* qb = q    + ((size_t)bh * QLEN + m0) * DK;
    const float* kb = k    + (size_t)bh * DK * SLEN;
    const float* vb = v    + (size_t)bh * SLEN * DK;
    const float* pb = prev + ((size_t)bh * QLEN + m0) * SLEN;
    float* sb = outS + ((size_t)bh * QLEN + m0) * SLEN;
    float* wb = outW + ((size_t)bh * QLEN + m0) * SLEN;
    float* ob = outO + ((size_t)bh * QLEN + m0) * DK;

    // ---- load Q tile (64x64) into smem as tf32 ----
    #pragma unroll
    for (int i = 0; i < 4; i++) {
        int f4 = tid + i * 256;              // 1024 float4s total
        int row = f4 >> 4, c4 = (f4 & 15) << 2;
        float4 x = *(const float4*)(qb + (size_t)row * DK + c4);
        sm.u.a.Qs[row * PAD + c4 + 0] = f2tf(x.x);
        sm.u.a.Qs[row * PAD + c4 + 1] = f2tf(x.y);
        sm.u.a.Qs[row * PAD + c4 + 2] = f2tf(x.z);
        sm.u.a.Qs[row * PAD + c4 + 3] = f2tf(x.w);
    }

    // ======== Phase A: S = Q@K * scale + prev, streamed to gmem ========
    for (int st = 0; st < SLEN / BN; st++) {
        #pragma unroll
        for (int i = 0; i < 4; i++) {        // K tile: 64 d-rows x 64 s-cols
            int f4 = tid + i * 256;
            int d = f4 >> 4, s4 = (f4 & 15) << 2;
            float4 x = *(const float4*)(kb + (size_t)d * SLEN + st * BN + s4);
            sm.u.a.Ks[d * PAD + s4 + 0] = f2tf(x.x);
            sm.u.a.Ks[d * PAD + s4 + 1] = f2tf(x.y);
            sm.u.a.Ks[d * PAD + s4 + 2] = f2tf(x.z);
            sm.u.a.Ks[d * PAD + s4 + 3] = f2tf(x.w);
        }
        __syncthreads();

        float acc[4][4] = {};
        #pragma unroll
        for (int ks = 0; ks < 8; ks++) {
            uint32_t a0 = sm.u.a.Qs[(wm * 16 + g    ) * PAD + ks * 8 + t4];
            uint32_t a1 = sm.u.a.Qs[(wm * 16 + g + 8) * PAD + ks * 8 + t4];
            uint32_t a2 = sm.u.a.Qs[(wm * 16 + g    ) * PAD + ks * 8 + t4 + 4];
            uint32_t a3 = sm.u.a.Qs[(wm * 16 + g + 8) * PAD + ks * 8 + t4 + 4];
            #pragma unroll
            for (int nt = 0; nt < 4; nt++) {
                uint32_t b0 = sm.u.a.Ks[(ks * 8 + t4    ) * PAD + wn * 32 + nt * 8 + g];
                uint32_t b1 = sm.u.a.Ks[(ks * 8 + t4 + 4) * PAD + wn * 32 + nt * 8 + g];
                mma_tf32(acc[nt], a0, a1, a2, a3, b0, b1);
            }
        }

        // epilogue: scale + prev, write scores
        #pragma unroll
        for (int nt = 0; nt < 4; nt++) {
            int col = st * BN + wn * 32 + nt * 8 + 2 * t4;
            int r0 = wm * 16 + g, r1 = r0 + 8;
            float2 p0 = *(const float2*)(pb + (size_t)r0 * SLEN + col);
            float2 p1 = *(const float2*)(pb + (size_t)r1 * SLEN + col);
            float2 s0 = make_float2(acc[nt][0] * scale + p0.x, acc[nt][1] * scale + p0.y);
            float2 s1 = make_float2(acc[nt][2] * scale + p1.x, acc[nt][3] * scale + p1.y);
            *(float2*)(sb + (size_t)r0 * SLEN + col) = s0;
            *(float2*)(sb + (size_t)r1 * SLEN + col) = s1;
        }
        __syncthreads();
    }

    // ======== Phase A2: per-row max and 1/sumexp (L2-hot re-read) ========
    {
        int row = tid >> 2, c = tid & 3;     // 4 threads per row
        const float4* sr = (const float4*)(sb + (size_t)row * SLEN);
        float m = -CUDART_INF_F;
        for (int i = c; i < SLEN / 4; i += 4) {
            float4 x = sr[i];
            m = fmaxf(m, fmaxf(fmaxf(x.x, x.y), fmaxf(x.z, x.w)));
        }
        m = fmaxf(m, __shfl_xor_sync(0xffffffffu, m, 1));
        m = fmaxf(m, __shfl_xor_sync(0xffffffffu, m, 2));
        float l = 0.f;
        for (int i = c; i < SLEN / 4; i += 4) {
            float4 x = sr[i];
            l += __expf(x.x - m) + __expf(x.y - m) + __expf(x.z - m) + __expf(x.w - m);
        }
        l += __shfl_xor_sync(0xffffffffu, l, 1);
        l += __shfl_xor_sync(0xffffffffu, l, 2);
        if (c == 0) { sm.rowmax[row] = m; sm.rowinv[row] = 1.f / l; }
    }
    __syncthreads();

    // ======== Phase B: P = softmax(S) written out; O += P@V ========
    float acc2[4][4] = {};
    for (int st = 0; st < SLEN / BN; st++) {
        #pragma unroll
        for (int i = 0; i < 4; i++) {        // P tile: 64 rows x 64 s
            int f4 = tid + i * 256;
            int row = f4 >> 4, s4 = (f4 & 15) << 2;
            float4 x = *(const float4*)(sb + (size_t)row * SLEN + st * BN + s4);
            float mr = sm.rowmax[row], il = sm.rowinv[row];
            float4 p;
            p.x = __expf(x.x - mr) * il;
            p.y = __expf(x.y - mr) * il;
            p.z = __expf(x.z - mr) * il;
            p.w = __expf(x.w - mr) * il;
            *(float4*)(wb + (size_t)row * SLEN + st * BN + s4) = p;
            sm.u.b.Ps[row * PAD + s4 + 0] = f2tf(p.x);
            sm.u.b.Ps[row * PAD + s4 + 1] = f2tf(p.y);
            sm.u.b.Ps[row * PAD + s4 + 2] = f2tf(p.z);
            sm.u.b.Ps[row * PAD + s4 + 3] = f2tf(p.w);
        }
        #pragma unroll
        for (int i = 0; i < 4; i++) {        // V tile: 64 s x 64 d
            int f4 = tid + i * 256;
            int srow = f4 >> 4, d4 = (f4 & 15) << 2;
            float4 x = *(const float4*)(vb + (size_t)(st * BN + srow) * DK + d4);
            sm.u.b.Vs[srow * PAD + d4 + 0] = f2tf(x.x);
            sm.u.b.Vs[srow * PAD + d4 + 1] = f2tf(x.y);
            sm.u.b.Vs[srow * PAD + d4 + 2] = f2tf(x.z);
            sm.u.b.Vs[srow * PAD + d4 + 3] = f2tf(x.w);
        }
        __syncthreads();

        #pragma unroll
        for (int ks = 0; ks < 8; ks++) {
            uint32_t a0 = sm.u.b.Ps[(wm * 16 + g    ) * PAD + ks * 8 + t4];
            uint32_t a1 = sm.u.b.Ps[(wm * 16 + g + 8) * PAD + ks * 8 + t4];
            uint32_t a2 = sm.u.b.Ps[(wm * 16 + g    ) * PAD + ks * 8 + t4 + 4];
            uint32_t a3 = sm.u.b.Ps[(wm * 16 + g + 8) * PAD + ks * 8 + t4 + 4];
            #pragma unroll
            for (int nt = 0; nt < 4; nt++) {
                uint32_t b0 = sm.u.b.Vs[(ks * 8 + t4    ) * PAD + wn * 32 + nt * 8 + g];
                uint32_t b1 = sm.u.b.Vs[(ks * 8 + t4 + 4) * PAD + wn * 32 + nt * 8 + g];
                mma_tf32(acc2[nt], a0, a1, a2, a3, b0, b1);
            }
        }
        __syncthreads();
    }

    // ---- write O ----
    #pragma unroll
    for (int nt = 0; nt < 4; nt++) {
        int col = wn * 32 + nt * 8 + 2 * t4;
        int r0 = wm * 16 + g, r1 = r0 + 8;
        *(float2*)(ob + (size_t)r0 * DK + col) = make_float2(acc2[nt][0], acc2[nt][1]);
        *(float2*)(ob + (size_t)r1 * DK + col) = make_float2(acc2[nt][2], acc2[nt][3]);
    }
}

extern "C" void kernel_launch(void* const* d_in, const int* in_sizes, int n_in,
                              void* d_out, int out_size)
{
    const float* q     = (const float*)d_in[0];
    const float* k     = (const float*)d_in[1];
    const float* v     = (const float*)d_in[2];
    const float* prev  = (const float*)d_in[3];
    const float* scale = (const float*)d_in[4];

    float* out  = (float*)d_out;
    float* outO = out;                                          // [2,16,1024,64]
    float* outW = out + (size_t)NBH * QLEN * DK;                // [2,16,1024,1024]
    float* outS = outW + (size_t)NBH * QLEN * SLEN;             // [2,16,1024,1024]

    dim3 grid(QLEN / BM, NBH);
    attn_kernel<<<grid, 256>>>(q, k, v, prev, scale, outO, outW, outS);
}

// round 2
// speedup vs baseline: 1.1903x; 1.1903x over previous
#include <cuda_runtime.h>
#include <cstdint>
#include <math_constants.h>

#define BM   64
#define BN   64
#define DK   64
#define SLEN 1024
#define QLEN 1024
#define NBH  32
#define NTILE (SLEN / BN)
#define KVSTRIDE 72   // fp32 K/V tile row stride (words): conflict-free B-frag LDS
#define PSTRIDE  68   // tf32 P tile row stride (words): conflict-free A-frag LDS

#define KV_WORDS (2 * 64 * KVSTRIDE)
#define PS_WORDS (64 * PSTRIDE)
#define DYN_BYTES ((KV_WORDS + PS_WORDS) * 4)

__device__ __forceinline__ uint32_t f2tf(float x) {
    uint32_t r; asm("cvt.rna.tf32.f32 %0, %1;" : "=r"(r) : "f"(x)); return r;
}

__device__ __forceinline__ void mma_tf32(float c[4],
    uint32_t a0, uint32_t a1, uint32_t a2, uint32_t a3,
    uint32_t b0, uint32_t b1)
{
    asm volatile(
        "mma.sync.aligned.m16n8k8.row.col.f32.tf32.tf32.f32 "
        "{%0,%1,%2,%3}, {%4,%5,%6,%7}, {%8,%9}, {%0,%1,%2,%3};"
        : "+f"(c[0]), "+f"(c[1]), "+f"(c[2]), "+f"(c[3])
        : "r"(a0), "r"(a1), "r"(a2), "r"(a3), "r"(b0), "r"(b1));
}

__device__ __forceinline__ void cp16(uint32_t saddr, const void* g) {
    asm volatile("cp.async.cg.shared.global [%0], [%1], 16;" :: "r"(saddr), "l"(g));
}

// Load one 64x64 fp32 tile (row stride gstride in gmem) into smem (stride KVSTRIDE).
__device__ __forceinline__ void tile_async(uint32_t sbase, const float* gbase,
                                           int gstride, int tid)
{
    #pragma unroll
    for (int i = 0; i < 4; i++) {
        int id  = tid + i * 256;            // 1024 16B chunks
        int row = id >> 4, cc = (id & 15) << 2;
        cp16(sbase + (uint32_t)(row * KVSTRIDE + cc) * 4,
             gbase + (size_t)row * gstride + cc);
    }
    asm volatile("cp.async.commit_group;");
}

__global__ void __launch_bounds__(256)
attn_kernel(const float* __restrict__ q, const float* __restrict__ k,
            const float* __restrict__ v, const float* __restrict__ prev,
            const float* __restrict__ scale_p,
            float* __restrict__ outO, float* __restrict__ outW,
            float* __restrict__ outS)
{
    extern __shared__ float dyn[];
    float*    kv = dyn;                       // 2 x 64 x KVSTRIDE fp32 (K or V tiles)
    uint32_t* Pp = (uint32_t*)(dyn + KV_WORDS); // 64 x PSTRIDE tf32 (P tile)
    __shared__ float rowmax[BM], rowinv[BM];
    __shared__ float pm[BM][2], pl[BM][2];

    const int tid  = threadIdx.x;
    const int bh   = blockIdx.y;
    const int m0   = blockIdx.x * BM;
    const int warp = tid >> 5, lane = tid & 31;
    const int g    = lane >> 2, t4 = lane & 3;
    const int wm   = warp & 3;
    const int wn   = warp >> 2;
    const float scale = scale_p[0];

    const float* qb = q    + ((size_t)bh * QLEN + m0) * DK;
    const float* kb = k    + (size_t)bh * DK * SLEN;
    const float* vb = v    + (size_t)bh * SLEN * DK;
    const float* pb = prev + ((size_t)bh * QLEN + m0) * SLEN;
    float* sb = outS + ((size_t)bh * QLEN + m0) * SLEN;
    float* wb = outW + ((size_t)bh * QLEN + m0) * SLEN;
    float* ob = outO + ((size_t)bh * QLEN + m0) * DK;

    const uint32_t kv_s = (uint32_t)__cvta_generic_to_shared(kv);
    const int r0 = wm * 16 + g, r1 = r0 + 8;
    const int bcol = wn * 32 + g;

    // ---- Q fragments straight from gmem into registers (scale folded: exact 2^-3) ----
    uint32_t qa[8][4];
    {
        const float* q0 = qb + (size_t)r0 * DK;
        const float* q1 = qb + (size_t)r1 * DK;
        #pragma unroll
        for (int ks = 0; ks < 8; ks++) {
            qa[ks][0] = f2tf(q0[ks * 8 + t4]     * scale);
            qa[ks][1] = f2tf(q1[ks * 8 + t4]     * scale);
            qa[ks][2] = f2tf(q0[ks * 8 + t4 + 4] * scale);
            qa[ks][3] = f2tf(q1[ks * 8 + t4 + 4] * scale);
        }
    }

    // ======== Phase A: S = Q@K + prev -> gmem, with online row max/sum ========
    float m0r = -CUDART_INF_F, m1r = -CUDART_INF_F, l0r = 0.f, l1r = 0.f;

    tile_async(kv_s, kb, SLEN, tid);   // K tile 0 -> buf 0

    #pragma unroll 1
    for (int st = 0; st < NTILE; st++) {
        const int cur = st & 1;
        if (st + 1 < NTILE) {
            tile_async(kv_s + (uint32_t)((cur ^ 1) * 64 * KVSTRIDE) * 4,
                       kb + (st + 1) * BN, SLEN, tid);
            asm volatile("cp.async.wait_group 1;");
        } else {
            asm volatile("cp.async.wait_group 0;");
        }
        __syncthreads();

        // prefetch prev for this tile (independent of MMA -> overlaps)
        float2 pv0[4], pv1[4];
        #pragma unroll
        for (int nt = 0; nt < 4; nt++) {
            int col = st * BN + wn * 32 + nt * 8 + 2 * t4;
            pv0[nt] = *(const float2*)(pb + (size_t)r0 * SLEN + col);
            pv1[nt] = *(const float2*)(pb + (size_t)r1 * SLEN + col);
        }

        const float* Kc = kv + cur * 64 * KVSTRIDE;
        float acc[4][4] = {};
        #pragma unroll
        for (int ks = 0; ks < 8; ks++) {
            #pragma unroll
            for (int nt = 0; nt < 4; nt++) {
                uint32_t b0 = f2tf(Kc[(ks * 8 + t4    ) * KVSTRIDE + bcol + nt * 8]);
                uint32_t b1 = f2tf(Kc[(ks * 8 + t4 + 4) * KVSTRIDE + bcol + nt * 8]);
                mma_tf32(acc[nt], qa[ks][0], qa[ks][1], qa[ks][2], qa[ks][3], b0, b1);
            }
        }

        // epilogue: add prev, write S, online stats
        float s0v[8], s1v[8];
        #pragma unroll
        for (int nt = 0; nt < 4; nt++) {
            int col = st * BN + wn * 32 + nt * 8 + 2 * t4;
            s0v[2*nt]   = acc[nt][0] + pv0[nt].x;
            s0v[2*nt+1] = acc[nt][1] + pv0[nt].y;
            s1v[2*nt]   = acc[nt][2] + pv1[nt].x;
            s1v[2*nt+1] = acc[nt][3] + pv1[nt].y;
            *(float2*)(sb + (size_t)r0 * SLEN + col) = make_float2(s0v[2*nt], s0v[2*nt+1]);
            *(float2*)(sb + (size_t)r1 * SLEN + col) = make_float2(s1v[2*nt], s1v[2*nt+1]);
        }
        float tm0 = s0v[0], tm1 = s1v[0];
        #pragma unroll
        for (int j = 1; j < 8; j++) { tm0 = fmaxf(tm0, s0v[j]); tm1 = fmaxf(tm1, s1v[j]); }
        float nm0 = fmaxf(m0r, tm0), nm1 = fmaxf(m1r, tm1);
        float e0 = 0.f, e1 = 0.f;
        #pragma unroll
        for (int j = 0; j < 8; j++) { e0 += __expf(s0v[j] - nm0); e1 += __expf(s1v[j] - nm1); }
        l0r = l0r * __expf(m0r - nm0) + e0;
        l1r = l1r * __expf(m1r - nm1) + e1;
        m0r = nm0; m1r = nm1;

        __syncthreads();
    }

    // ---- cross-thread softmax stat reduction ----
    #pragma unroll
    for (int off = 1; off <= 2; off <<= 1) {
        float om = __shfl_xor_sync(0xffffffffu, m0r, off);
        float ol = __shfl_xor_sync(0xffffffffu, l0r, off);
        float nm = fmaxf(m0r, om);
        l0r = l0r * __expf(m0r - nm) + ol * __expf(om - nm);
        m0r = nm;
        om = __shfl_xor_sync(0xffffffffu, m1r, off);
        ol = __shfl_xor_sync(0xffffffffu, l1r, off);
        nm = fmaxf(m1r, om);
        l1r = l1r * __expf(m1r - nm) + ol * __expf(om - nm);
        m1r = nm;
    }
    if (t4 == 0) {
        pm[r0][wn] = m0r; pl[r0][wn] = l0r;
        pm[r1][wn] = m1r; pl[r1][wn] = l1r;
    }
    __syncthreads();
    if (tid < BM) {
        float ma = pm[tid][0], mb = pm[tid][1];
        float nm = fmaxf(ma, mb);
        float l  = pl[tid][0] * __expf(ma - nm) + pl[tid][1] * __expf(mb - nm);
        rowmax[tid] = nm;
        rowinv[tid] = 1.f / l;
    }
    __syncthreads();

    // ======== Phase B: P = softmax(S) -> gmem; O += P @ V ========
    float acc2[4][4] = {};
    tile_async(kv_s, vb, DK, tid);     // V tile 0 -> buf 0

    #pragma unroll 1
    for (int st = 0; st < NTILE; st++) {
        const int cur = st & 1;
        if (st + 1 < NTILE)
            tile_async(kv_s + (uint32_t)((cur ^ 1) * 64 * KVSTRIDE) * 4,
                       vb + (size_t)(st + 1) * BN * DK, DK, tid);

        // P tile: read S (L2-hot), exp-normalize, write P, stash tf32 in smem
        #pragma unroll
        for (int i = 0; i < 4; i++) {
            int f4  = tid + i * 256;
            int row = f4 >> 4, c4 = (f4 & 15) << 2;
            float4 x = *(const float4*)(sb + (size_t)row * SLEN + st * BN + c4);
            float mr = rowmax[row], il = rowinv[row];
            float4 p;
            p.x = __expf(x.x - mr) * il;
            p.y = __expf(x.y - mr) * il;
            p.z = __expf(x.z - mr) * il;
            p.w = __expf(x.w - mr) * il;
            *(float4*)(wb + (size_t)row * SLEN + st * BN + c4) = p;
            uint4 w4;
            w4.x = f2tf(p.x); w4.y = f2tf(p.y); w4.z = f2tf(p.z); w4.w = f2tf(p.w);
            *(uint4*)(Pp + row * PSTRIDE + c4) = w4;
        }

        if (st + 1 < NTILE) asm volatile("cp.async.wait_group 1;");
        else                asm volatile("cp.async.wait_group 0;");
        __syncthreads();

        const float* Vc = kv + cur * 64 * KVSTRIDE;
        #pragma unroll
        for (int ks = 0; ks < 8; ks++) {
            uint32_t a0 = Pp[(r0    ) * PSTRIDE + ks * 8 + t4];
            uint32_t a1 = Pp[(r1    ) * PSTRIDE + ks * 8 + t4];
            uint32_t a2 = Pp[(r0    ) * PSTRIDE + ks * 8 + t4 + 4];
            uint32_t a3 = Pp[(r1    ) * PSTRIDE + ks * 8 + t4 + 4];
            #pragma unroll
            for (int nt = 0; nt < 4; nt++) {
                uint32_t b0 = f2tf(Vc[(ks * 8 + t4    ) * KVSTRIDE + bcol + nt * 8]);
                uint32_t b1 = f2tf(Vc[(ks * 8 + t4 + 4) * KVSTRIDE + bcol + nt * 8]);
                mma_tf32(acc2[nt], a0, a1, a2, a3, b0, b1);
            }
        }
        __syncthreads();
    }

    // ---- write O ----
    #pragma unroll
    for (int nt = 0; nt < 4; nt++) {
        int col = wn * 32 + nt * 8 + 2 * t4;
        *(float2*)(ob + (size_t)r0 * DK + col) = make_float2(acc2[nt][0], acc2[nt][1]);
        *(float2*)(ob + (size_t)r1 * DK + col) = make_float2(acc2[nt][2], acc2[nt][3]);
    }
}

extern "C" void kernel_launch(void* const* d_in, const int* in_sizes, int n_in,
                              void* d_out, int out_size)
{
    const float* q     = (const float*)d_in[0];
    const float* k     = (const float*)d_in[1];
    const float* v     = (const float*)d_in[2];
    const float* prev  = (const float*)d_in[3];
    const float* scale = (const float*)d_in[4];

    float* out  = (float*)d_out;
    float* outO = out;                                   // [2,16,1024,64]
    float* outW = out + (size_t)NBH * QLEN * DK;         // [2,16,1024,1024]
    float* outS = outW + (size_t)NBH * QLEN * SLEN;      // [2,16,1024,1024]

    cudaFuncSetAttribute(attn_kernel,
                         cudaFuncAttributeMaxDynamicSharedMemorySize, DYN_BYTES);
    dim3 grid(QLEN / BM, NBH);
    attn_kernel<<<grid, 256, DYN_BYTES>>>(q, k, v, prev, scale, outO, outW, outS);
}

// round 3
// speedup vs baseline: 1.4683x; 1.2336x over previous
#include <cuda_runtime.h>
#include <cstdint>
#include <math_constants.h>

#define BM   64
#define BN   64
#define DK   64
#define SLEN 1024
#define QLEN 1024
#define NBH  32
#define NTILE (SLEN / BN)
#define KVSTRIDE 72   // fp32 K/V tile row stride (words): conflict-free B-frag LDS
#define PSTRIDE  68   // tf32 Q/P tile row stride (words): conflict-free A-frag LDS

#define KV_WORDS (2 * 64 * KVSTRIDE)
#define PS_WORDS (64 * PSTRIDE)
#define DYN_BYTES ((KV_WORDS + PS_WORDS) * 4)

__device__ __forceinline__ uint32_t f2tf(float x) {
    uint32_t r; asm("cvt.rna.tf32.f32 %0, %1;" : "=r"(r) : "f"(x)); return r;
}

__device__ __forceinline__ void mma_tf32(float c[4],
    uint32_t a0, uint32_t a1, uint32_t a2, uint32_t a3,
    uint32_t b0, uint32_t b1)
{
    asm volatile(
        "mma.sync.aligned.m16n8k8.row.col.f32.tf32.tf32.f32 "
        "{%0,%1,%2,%3}, {%4,%5,%6,%7}, {%8,%9}, {%0,%1,%2,%3};"
        : "+f"(c[0]), "+f"(c[1]), "+f"(c[2]), "+f"(c[3])
        : "r"(a0), "r"(a1), "r"(a2), "r"(a3), "r"(b0), "r"(b1));
}

__device__ __forceinline__ void cp16(uint32_t saddr, const void* g) {
    asm volatile("cp.async.cg.shared.global [%0], [%1], 16;" :: "r"(saddr), "l"(g));
}

// Load one 64x64 fp32 tile (row stride gstride in gmem) into smem (stride KVSTRIDE).
__device__ __forceinline__ void tile_async(uint32_t sbase, const float* gbase,
                                           int gstride, int tid)
{
    #pragma unroll
    for (int i = 0; i < 4; i++) {
        int id  = tid + i * 256;            // 1024 16B chunks
        int row = id >> 4, cc = (id & 15) << 2;
        cp16(sbase + (uint32_t)(row * KVSTRIDE + cc) * 4,
             gbase + (size_t)row * gstride + cc);
    }
    asm volatile("cp.async.commit_group;");
}

__global__ void __launch_bounds__(256, 4)
attn_kernel(const float* __restrict__ q, const float* __restrict__ k,
            const float* __restrict__ v, const float* __restrict__ prev,
            const float* __restrict__ scale_p,
            float* __restrict__ outO, float* __restrict__ outW,
            float* __restrict__ outS)
{
    extern __shared__ float dyn[];
    float*    kv = dyn;                         // 2 x 64 x KVSTRIDE fp32 (K or V)
    uint32_t* QP = (uint32_t*)(dyn + KV_WORDS); // 64 x PSTRIDE tf32 (Q in A, P in B)
    __shared__ float rowmax[BM], rowinv[BM];
    __shared__ float pm[BM][2], pl[BM][2];

    const int tid  = threadIdx.x;
    const int bh   = blockIdx.y;
    const int m0   = blockIdx.x * BM;
    const int warp = tid >> 5, lane = tid & 31;
    const int g    = lane >> 2, t4 = lane & 3;
    const int wm   = warp & 3;
    const int wn   = warp >> 2;
    const float scale = scale_p[0];

    const float* qb = q    + ((size_t)bh * QLEN + m0) * DK;
    const float* kb = k    + (size_t)bh * DK * SLEN;
    const float* vb = v    + (size_t)bh * SLEN * DK;
    const float* pb = prev + ((size_t)bh * QLEN + m0) * SLEN;
    float* sb = outS + ((size_t)bh * QLEN + m0) * SLEN;
    float* wb = outW + ((size_t)bh * QLEN + m0) * SLEN;
    float* ob = outO + ((size_t)bh * QLEN + m0) * DK;

    const uint32_t kv_s = (uint32_t)__cvta_generic_to_shared(kv);
    const int r0 = wm * 16 + g, r1 = r0 + 8;
    const int bcol = wn * 32 + g;

    tile_async(kv_s, kb, SLEN, tid);   // K tile 0 -> buf 0

    // ---- Q tile into smem as tf32 (scale folded in; aliases P buffer) ----
    #pragma unroll
    for (int i = 0; i < 4; i++) {
        int f4 = tid + i * 256;
        int row = f4 >> 4, c4 = (f4 & 15) << 2;
        float4 x = *(const float4*)(qb + (size_t)row * DK + c4);
        uint4 w;
        w.x = f2tf(x.x * scale); w.y = f2tf(x.y * scale);
        w.z = f2tf(x.z * scale); w.w = f2tf(x.w * scale);
        *(uint4*)(QP + row * PSTRIDE + c4) = w;
    }

    // ======== Phase A: S = Q@K + prev -> gmem, online row max/sum ========
    float m0r = -CUDART_INF_F, m1r = -CUDART_INF_F, l0r = 0.f, l1r = 0.f;

    #pragma unroll 1
    for (int st = 0; st < NTILE; st++) {
        const int cur = st & 1;
        if (st + 1 < NTILE) {
            tile_async(kv_s + (uint32_t)((cur ^ 1) * 64 * KVSTRIDE) * 4,
                       kb + (st + 1) * BN, SLEN, tid);
            asm volatile("cp.async.wait_group 1;");
        } else {
            asm volatile("cp.async.wait_group 0;");
        }
        __syncthreads();

        // prefetch prev for this tile (independent of MMA -> overlaps)
        float2 pv0[4], pv1[4];
        #pragma unroll
        for (int nt = 0; nt < 4; nt++) {
            int col = st * BN + wn * 32 + nt * 8 + 2 * t4;
            pv0[nt] = *(const float2*)(pb + (size_t)r0 * SLEN + col);
            pv1[nt] = *(const float2*)(pb + (size_t)r1 * SLEN + col);
        }

        const float* Kc = kv + cur * 64 * KVSTRIDE;
        float acc[4][4] = {};
        #pragma unroll
        for (int ks = 0; ks < 8; ks++) {
            uint32_t a0 = QP[r0 * PSTRIDE + ks * 8 + t4];
            uint32_t a1 = QP[r1 * PSTRIDE + ks * 8 + t4];
            uint32_t a2 = QP[r0 * PSTRIDE + ks * 8 + t4 + 4];
            uint32_t a3 = QP[r1 * PSTRIDE + ks * 8 + t4 + 4];
            #pragma unroll
            for (int nt = 0; nt < 4; nt++) {
                uint32_t b0 = f2tf(Kc[(ks * 8 + t4    ) * KVSTRIDE + bcol + nt * 8]);
                uint32_t b1 = f2tf(Kc[(ks * 8 + t4 + 4) * KVSTRIDE + bcol + nt * 8]);
                mma_tf32(acc[nt], a0, a1, a2, a3, b0, b1);
            }
        }

        // epilogue in-place: S = acc + prev, write S, online stats
        #pragma unroll
        for (int nt = 0; nt < 4; nt++) {
            int col = st * BN + wn * 32 + nt * 8 + 2 * t4;
            acc[nt][0] += pv0[nt].x; acc[nt][1] += pv0[nt].y;
            acc[nt][2] += pv1[nt].x; acc[nt][3] += pv1[nt].y;
            *(float2*)(sb + (size_t)r0 * SLEN + col) = make_float2(acc[nt][0], acc[nt][1]);
            *(float2*)(sb + (size_t)r1 * SLEN + col) = make_float2(acc[nt][2], acc[nt][3]);
        }
        float tm0 = acc[0][0], tm1 = acc[0][2];
        #pragma unroll
        for (int nt = 0; nt < 4; nt++) {
            tm0 = fmaxf(tm0, fmaxf(acc[nt][0], acc[nt][1]));
            tm1 = fmaxf(tm1, fmaxf(acc[nt][2], acc[nt][3]));
        }
        float nm0 = fmaxf(m0r, tm0), nm1 = fmaxf(m1r, tm1);
        float e0 = 0.f, e1 = 0.f;
        #pragma unroll
        for (int nt = 0; nt < 4; nt++) {
            e0 += __expf(acc[nt][0] - nm0) + __expf(acc[nt][1] - nm0);
            e1 += __expf(acc[nt][2] - nm1) + __expf(acc[nt][3] - nm1);
        }
        l0r = l0r * __expf(m0r - nm0) + e0;
        l1r = l1r * __expf(m1r - nm1) + e1;
        m0r = nm0; m1r = nm1;

        __syncthreads();
    }

    // ---- cross-thread softmax stat reduction ----
    #pragma unroll
    for (int off = 1; off <= 2; off <<= 1) {
        float om = __shfl_xor_sync(0xffffffffu, m0r, off);
        float ol = __shfl_xor_sync(0xffffffffu, l0r, off);
        float nm = fmaxf(m0r, om);
        l0r = l0r * __expf(m0r - nm) + ol * __expf(om - nm);
        m0r = nm;
        om = __shfl_xor_sync(0xffffffffu, m1r, off);
        ol = __shfl_xor_sync(0xffffffffu, l1r, off);
        nm = fmaxf(m1r, om);
        l1r = l1r * __expf(m1r - nm) + ol * __expf(om - nm);
        m1r = nm;
    }
    if (t4 == 0) {
        pm[r0][wn] = m0r; pl[r0][wn] = l0r;
        pm[r1][wn] = m1r; pl[r1][wn] = l1r;
    }
    __syncthreads();
    if (tid < BM) {
        float ma = pm[tid][0], mb = pm[tid][1];
        float nm = fmaxf(ma, mb);
        float l  = pl[tid][0] * __expf(ma - nm) + pl[tid][1] * __expf(mb - nm);
        rowmax[tid] = nm;
        rowinv[tid] = 1.f / l;
    }
    __syncthreads();

    // ======== Phase B: P = softmax(S) -> gmem; O += P @ V ========
    float acc2[4][4] = {};
    tile_async(kv_s, vb, DK, tid);     // V tile 0 -> buf 0

    #pragma unroll 1
    for (int st = 0; st < NTILE; st++) {
        const int cur = st & 1;
        if (st + 1 < NTILE)
            tile_async(kv_s + (uint32_t)((cur ^ 1) * 64 * KVSTRIDE) * 4,
                       vb + (size_t)(st + 1) * BN * DK, DK, tid);

        // P tile: read S (L2-hot), exp-normalize, write P, stash tf32 in smem
        #pragma unroll
        for (int i = 0; i < 4; i++) {
            int f4  = tid + i * 256;
            int row = f4 >> 4, c4 = (f4 & 15) << 2;
            float4 x = *(const float4*)(sb + (size_t)row * SLEN + st * BN + c4);
            float mr = rowmax[row], il = rowinv[row];
            float4 p;
            p.x = __expf(x.x - mr) * il;
            p.y = __expf(x.y - mr) * il;
            p.z = __expf(x.z - mr) * il;
            p.w = __expf(x.w - mr) * il;
            *(float4*)(wb + (size_t)row * SLEN + st * BN + c4) = p;
            uint4 w4;
            w4.x = f2tf(p.x); w4.y = f2tf(p.y); w4.z = f2tf(p.z); w4.w = f2tf(p.w);
            *(uint4*)(QP + row * PSTRIDE + c4) = w4;
        }

        if (st + 1 < NTILE) asm volatile("cp.async.wait_group 1;");
        else                asm volatile("cp.async.wait_group 0;");
        __syncthreads();

        const float* Vc = kv + cur * 64 * KVSTRIDE;
        #pragma unroll
        for (int ks = 0; ks < 8; ks++) {
            uint32_t a0 = QP[r0 * PSTRIDE + ks * 8 + t4];
            uint32_t a1 = QP[r1 * PSTRIDE + ks * 8 + t4];
            uint32_t a2 = QP[r0 * PSTRIDE + ks * 8 + t4 + 4];
            uint32_t a3 = QP[r1 * PSTRIDE + ks * 8 + t4 + 4];
            #pragma unroll
            for (int nt = 0; nt < 4; nt++) {
                uint32_t b0 = f2tf(Vc[(ks * 8 + t4    ) * KVSTRIDE + bcol + nt * 8]);
                uint32_t b1 = f2tf(Vc[(ks * 8 + t4 + 4) * KVSTRIDE + bcol + nt * 8]);
                mma_tf32(acc2[nt], a0, a1, a2, a3, b0, b1);
            }
        }
        __syncthreads();
    }

    // ---- write O ----
    #pragma unroll
    for (int nt = 0; nt < 4; nt++) {
        int col = wn * 32 + nt * 8 + 2 * t4;
        *(float2*)(ob + (size_t)r0 * DK + col) = make_float2(acc2[nt][0], acc2[nt][1]);
        *(float2*)(ob + (size_t)r1 * DK + col) = make_float2(acc2[nt][2], acc2[nt][3]);
    }
}

extern "C" void kernel_launch(void* const* d_in, const int* in_sizes, int n_in,
                              void* d_out, int out_size)
{
    const float* q     = (const float*)d_in[0];
    const float* k     = (const float*)d_in[1];
    const float* v     = (const float*)d_in[2];
    const float* prev  = (const float*)d_in[3];
    const float* scale = (const float*)d_in[4];

    float* out  = (float*)d_out;
    float* outO = out;                                   // [2,16,1024,64]
    float* outW = out + (size_t)NBH * QLEN * DK;         // [2,16,1024,1024]
    float* outS = outW + (size_t)NBH * QLEN * SLEN;      // [2,16,1024,1024]

    cudaFuncSetAttribute(attn_kernel,
                         cudaFuncAttributeMaxDynamicSharedMemorySize, DYN_BYTES);
    dim3 grid(QLEN / BM, NBH);
    attn_kernel<<<grid, 256, DYN_BYTES>>>(q, k, v, prev, scale, outO, outW, outS);
}